// round 3
// baseline (speedup 1.0000x reference)
#include <cuda_runtime.h>
#include <math.h>
#define LL 4096

__device__ __align__(16) float g_xz  [16384*384];
__device__ __align__(16) float g_xi  [768*LL];
__device__ __align__(16) float g_xc  [768*LL];
__device__ __align__(16) float g_xcT [768*LL];
__device__ __align__(16) float g_xdbl[16*LL*40];
__device__ __align__(16) float g_delta[16*192*LL];
__device__ __align__(16) float g_ys  [16*192*LL];
__device__ __align__(16) float g_ysum[768*LL];
__device__ __align__(16) float g_ygt [16384*192];
__device__ __align__(16) float g_hcl [16384*768];
__device__ __align__(16) float g_hc2 [16384*768];
__device__ __align__(16) float g_hn  [16384*768];
__device__ __align__(16) float g_weff[25*768];

__device__ __forceinline__ float siluf(float v){ return v/(1.f+__expf(-v)); }

// C[M,N] = A[M,K] @ W[N,K]^T. MODE 0: plain, 1: bias+silu, 2: C += skip[0]*(acc+bias)
template<int MODE>
__global__ __launch_bounds__(256) void sgemm_nt(
  const float* __restrict__ A, const float* __restrict__ W, float* __restrict__ C,
  int M, int N, int K, const float* __restrict__ bias, const float* __restrict__ skip)
{
  __shared__ float As[16][132];
  __shared__ float Ws[16][68];
  int tid=threadIdx.x, m0=blockIdx.y*128, n0=blockIdx.x*64;
  int tx=tid&15, ty=tid>>4, lr=tid>>2, lc=(tid&3)*4;
  float acc[8][4];
  #pragma unroll
  for(int i=0;i<8;i++)
    #pragma unroll
    for(int j=0;j<4;j++) acc[i][j]=0.f;
  for(int k0=0;k0<K;k0+=16){
    #pragma unroll
    for(int i=0;i<2;i++){
      int row=lr+i*64;
      float4 v=*(const float4*)(A+(size_t)(m0+row)*K+k0+lc);
      As[lc][row]=v.x; As[lc+1][row]=v.y; As[lc+2][row]=v.z; As[lc+3][row]=v.w;
    }
    { int row=n0+lr;
      float4 v=make_float4(0,0,0,0);
      if(row<N) v=*(const float4*)(W+(size_t)row*K+k0+lc);
      Ws[lc][lr]=v.x; Ws[lc+1][lr]=v.y; Ws[lc+2][lr]=v.z; Ws[lc+3][lr]=v.w; }
    __syncthreads();
    #pragma unroll
    for(int kk=0;kk<16;kk++){
      float4 a0=*(const float4*)&As[kk][ty*8], a1=*(const float4*)&As[kk][ty*8+4];
      float4 w0=*(const float4*)&Ws[kk][tx*4];
      float af[8]={a0.x,a0.y,a0.z,a0.w,a1.x,a1.y,a1.z,a1.w};
      float wf[4]={w0.x,w0.y,w0.z,w0.w};
      #pragma unroll
      for(int i=0;i<8;i++)
        #pragma unroll
        for(int j=0;j<4;j++) acc[i][j]=fmaf(af[i],wf[j],acc[i][j]);
    }
    __syncthreads();
  }
  #pragma unroll
  for(int i=0;i<8;i++){
    int m=m0+ty*8+i;
    #pragma unroll
    for(int j=0;j<4;j++){
      int n=n0+tx*4+j; if(n>=N) continue;
      float v=acc[i][j]; size_t idx=(size_t)m*N+n;
      if(MODE==0) C[idx]=v;
      else if(MODE==1){ v+=bias[n]; C[idx]=siluf(v); }
      else C[idx]+=skip[0]*(v+bias[n]);
    }
  }
}

// xz[:, :192] -> xi [b][c][l]
__global__ void t_xi(){
  __shared__ float t[32][33];
  int b=blockIdx.z, c0=blockIdx.x*32, l0=blockIdx.y*32, tx=threadIdx.x, ty=threadIdx.y;
  for(int i=0;i<4;i++) t[ty+i*8][tx]=g_xz[((size_t)b*LL+l0+ty+i*8)*384+c0+tx];
  __syncthreads();
  for(int i=0;i<4;i++) g_xi[((size_t)b*192+c0+ty+i*8)*LL+l0+tx]=t[tx][ty+i*8];
}

__global__ void conv3(const float* __restrict__ cw, const float* __restrict__ cb){
  int id=blockIdx.x*256+threadIdx.x; if(id>=768*LL) return;
  int l=id&4095, c=(id>>12)%192, h=l>>6, w=l&63;
  float s=cb[c];
  const float* base=g_xi+(size_t)(id-l);
  #pragma unroll
  for(int dy=0;dy<3;dy++){ int hh=h+dy-1; if(hh<0||hh>63) continue;
    #pragma unroll
    for(int dx=0;dx<3;dx++){ int ww=w+dx-1; if(ww<0||ww>63) continue;
      s+=base[hh*64+ww]*cw[c*9+dy*3+dx]; } }
  g_xc[id]=siluf(s);
}

__global__ void t_hw(){
  __shared__ float t[32][33];
  int bc=blockIdx.z, w0=blockIdx.x*32, h0=blockIdx.y*32, tx=threadIdx.x, ty=threadIdx.y;
  const float* s=g_xc+(size_t)bc*LL; float* d=g_xcT+(size_t)bc*LL;
  for(int i=0;i<4;i++) t[ty+i*8][tx]=s[(h0+ty+i*8)*64+w0+tx];
  __syncthreads();
  for(int i=0;i<4;i++) d[(w0+ty+i*8)*64+h0+tx]=t[tx][ty+i*8];
}

// x_dbl[bk][l][40]: cols 0..5 dts, 8..39 B/C interleaved (Bn at 8+2n, Cn at 9+2n)
__global__ __launch_bounds__(256) void xproj(const float* __restrict__ xpw){
  __shared__ float Xs[16][196];
  __shared__ float Wsm[38*192];
  int bk=blockIdx.y, b=bk>>2, k=bk&3, l0=blockIdx.x*16, tid=threadIdx.x;
  const float* src=(k&1)?g_xcT:g_xc; bool flip=(k>=2);
  for(int i=tid;i<38*192;i+=256) Wsm[i]=xpw[k*38*192+i];
  for(int i=tid;i<192*16;i+=256){ int d=i>>4, li=i&15;
    int lf=flip?(4095-(l0+li)):(l0+li);
    Xs[li][d]=src[((size_t)b*192+d)*LL+lf]; }
  __syncthreads();
  for(int o=tid;o<38*16;o+=256){ int c=o>>4, li=o&15;
    const float* wr=Wsm+c*192; const float* xr=Xs[li]; float s=0.f;
    #pragma unroll 8
    for(int d=0;d<192;d+=4){ float4 wv=*(const float4*)(wr+d), xv=*(const float4*)(xr+d);
      s+=wv.x*xv.x+wv.y*xv.y+wv.z*xv.z+wv.w*xv.w; }
    int col=(c<6)?c:(c<22?(8+2*(c-6)):(9+2*(c-22)));
    g_xdbl[((size_t)bk*LL+l0+li)*40+col]=s; }
}

__global__ __launch_bounds__(256) void deltak(const float* __restrict__ dtw, const float* __restrict__ dtb){
  int bk=blockIdx.y, l0=blockIdx.x*64, k=bk&3, tid=threadIdx.x;
  __shared__ float dts[64][6];
  for(int i=tid;i<64*6;i+=256) dts[i/6][i%6]=g_xdbl[((size_t)bk*LL+l0+i/6)*40+i%6];
  __syncthreads();
  for(int i=tid;i<192*64;i+=256){ int d=i>>6, li=i&63;
    float s=dtb[k*192+d];
    #pragma unroll
    for(int r=0;r<6;r++) s+=dts[li][r]*dtw[(k*192+d)*6+r];
    s=(s>20.f)?s:log1pf(__expf(s));
    g_delta[((size_t)bk*192+d)*LL+l0+li]=s; }
}

__global__ __launch_bounds__(128) void scan(const float* __restrict__ A_logs, const float* __restrict__ Ds){
  __shared__ float ybuf[4][2][32];
  int wIB=threadIdx.x>>5, lane=threadIdx.x&31;
  int wg=blockIdx.x*4+wIB, dpair=wg%96, bk=wg/96, b=bk>>2, k=bk&3;
  int half=lane>>4, n=lane&15, d=dpair*2+half, kd=k*192+d;
  float Av=-__expf(A_logs[kd*16+n]), Dv=Ds[kd];
  const float* xsrc=((k&1)?g_xcT:g_xc)+((size_t)b*192+d)*LL;
  const float* dsrc=g_delta+((size_t)bk*192+d)*LL;
  const float* xdb=g_xdbl+(size_t)bk*LL*40;
  bool flip=(k>=2);
  float h=0.f;
  for(int l0=0;l0<LL;l0+=32){
    #pragma unroll
    for(int s4=0;s4<32;s4+=4){
      int lb=l0+s4;
      float4 d4=*(const float4*)(dsrc+lb);
      float dls[4]={d4.x,d4.y,d4.z,d4.w}, xv[4];
      if(!flip){ float4 x4=*(const float4*)(xsrc+lb); xv[0]=x4.x;xv[1]=x4.y;xv[2]=x4.z;xv[3]=x4.w; }
      else     { float4 x4=*(const float4*)(xsrc+4092-lb); xv[0]=x4.w;xv[1]=x4.z;xv[2]=x4.y;xv[3]=x4.x; }
      #pragma unroll
      for(int i=0;i<4;i++){
        float2 bc=*(const float2*)(xdb+(size_t)(lb+i)*40+8+2*n);
        h=h*__expf(dls[i]*Av)+(dls[i]*xv[i])*bc.x;
        float yp=h*bc.y;
        yp+=__shfl_xor_sync(~0u,yp,1); yp+=__shfl_xor_sync(~0u,yp,2);
        yp+=__shfl_xor_sync(~0u,yp,4); yp+=__shfl_xor_sync(~0u,yp,8);
        if(n==0) ybuf[wIB][half][s4+i]=yp+Dv*xv[i];
      }
    }
    __syncwarp();
    #pragma unroll
    for(int hh=0;hh<2;hh++){
      size_t ob=(((size_t)k*4+b)*192+dpair*2+hh)*LL;
      int pos=flip?(4095-(l0+lane)):(l0+lane);
      g_ys[ob+pos]=ybuf[wIB][hh][lane];
    }
    __syncwarp();
  }
}

// ysum[b][c][h*64+w] = Y0+Y2 at hw + transpose(Y1+Y3)
__global__ void combine(){
  __shared__ float t[32][33];
  int bc=blockIdx.z, w0=blockIdx.x*32, h0=blockIdx.y*32, tx=threadIdx.x, ty=threadIdx.y;
  const float* Y0=g_ys+(size_t)bc*LL;         const float* Y1=g_ys+(size_t)(768+bc)*LL;
  const float* Y2=g_ys+(size_t)(1536+bc)*LL;  const float* Y3=g_ys+(size_t)(2304+bc)*LL;
  for(int i=0;i<4;i++){ int wl=ty+i*8, j=(w0+wl)*64+h0+tx; t[wl][tx]=Y1[j]+Y3[j]; }
  __syncthreads();
  float* o=g_ysum+(size_t)bc*LL;
  for(int i=0;i<4;i++){ int hl=ty+i*8, l=(h0+hl)*64+w0+tx; o[l]=t[tx][hl]+Y0[l]+Y2[l]; }
}

__global__ __launch_bounds__(256) void ln_gate(const float* __restrict__ g, const float* __restrict__ beta){
  __shared__ float t[192][33];
  int b=blockIdx.y, l0=blockIdx.x*32, tid=threadIdx.x;
  for(int i=tid;i<192*32;i+=256) t[i>>5][i&31]=g_ysum[((size_t)b*192+(i>>5))*LL+l0+(i&31)];
  __syncthreads();
  int warp=tid>>5, lane=tid&31;
  for(int q=0;q<4;q++){
    int li=warp*4+q, l=l0+li;
    float s=0.f,s2=0.f,v[6];
    #pragma unroll
    for(int i=0;i<6;i++){ v[i]=t[lane+32*i][li]; s+=v[i]; s2+=v[i]*v[i]; }
    #pragma unroll
    for(int o=16;o;o>>=1){ s+=__shfl_xor_sync(~0u,s,o); s2+=__shfl_xor_sync(~0u,s2,o); }
    float mean=s/192.f, var=s2/192.f-mean*mean, rstd=rsqrtf(var+1e-5f);
    #pragma unroll
    for(int i=0;i<6;i++){ int c=lane+32*i;
      float zz=g_xz[((size_t)b*LL+l)*384+192+c];
      g_ygt[((size_t)b*LL+l)*192+c]=((v[i]-mean)*rstd*g[c]+beta[c])*siluf(zz); }
  }
}

__global__ void prep_weff(const float* __restrict__ d1,const float* __restrict__ d3,const float* __restrict__ d5){
  int c=blockIdx.x*256+threadIdx.x; if(c>=768) return;
  for(int t=0;t<25;t++){ int dy=t/5,dx=t%5;
    float w=d5[c*25+t];
    if(dy>=1&&dy<=3&&dx>=1&&dx<=3) w+=d3[c*9+(dy-1)*3+(dx-1)];
    if(t==12) w+=d1[c]+1.0f;
    g_weff[t*768+c]=w; }
}

__global__ __launch_bounds__(512) void conv5(){
  __shared__ float4 tile[8][12][16];
  int cg=blockIdx.x, w0=blockIdx.y*8, b=blockIdx.z>>4, h0=(blockIdx.z&15)*4;
  int tid=threadIdx.x+threadIdx.y*16+threadIdx.z*128;
  for(int t=tid;t<8*12*16;t+=512){
    int r=t/192, cc=(t%192)/16, c4=t&15;
    int h=h0-2+r, w=w0-2+cc;
    float4 v=make_float4(0,0,0,0);
    if(h>=0&&h<64&&w>=0&&w<64)
      v=*(const float4*)(g_hcl+((size_t)(b*LL+h*64+w))*768+cg*64+c4*4);
    tile[r][cc][c4]=v;
  }
  __syncthreads();
  int c4=threadIdx.x, iw=threadIdx.y, ih=threadIdx.z;
  float4 a=make_float4(0,0,0,0);
  #pragma unroll
  for(int dy=0;dy<5;dy++)
    #pragma unroll
    for(int dx=0;dx<5;dx++){
      float4 xv=tile[ih+dy][iw+dx][c4];
      float4 wv=*(const float4*)(g_weff+(dy*5+dx)*768+cg*64+c4*4);
      a.x=fmaf(xv.x,wv.x,a.x); a.y=fmaf(xv.y,wv.y,a.y);
      a.z=fmaf(xv.z,wv.z,a.z); a.w=fmaf(xv.w,wv.w,a.w);
    }
  *(float4*)(g_hc2+((size_t)(b*LL+(h0+ih)*64+w0+iw))*768+cg*64+c4*4)=a;
}

__global__ __launch_bounds__(256) void ln768(const float* __restrict__ g, const float* __restrict__ beta){
  int m=blockIdx.x;
  const float* row=g_hc2+(size_t)m*768;
  float v[3], s=0.f, s2=0.f;
  #pragma unroll
  for(int i=0;i<3;i++){ v[i]=row[threadIdx.x+256*i]; s+=v[i]; s2+=v[i]*v[i]; }
  #pragma unroll
  for(int o=16;o;o>>=1){ s+=__shfl_xor_sync(~0u,s,o); s2+=__shfl_xor_sync(~0u,s2,o); }
  __shared__ float red[2][8];
  int warp=threadIdx.x>>5, lane=threadIdx.x&31;
  if(lane==0){ red[0][warp]=s; red[1][warp]=s2; }
  __syncthreads();
  float ts=0.f,ts2=0.f;
  #pragma unroll
  for(int i=0;i<8;i++){ ts+=red[0][i]; ts2+=red[1][i]; }
  float mean=ts/768.f, var=ts2/768.f-mean*mean, rstd=rsqrtf(var+1e-5f);
  #pragma unroll
  for(int i=0;i<3;i++){ int c=threadIdx.x+256*i;
    g_hn[(size_t)m*768+c]=(v[i]-mean)*rstd*g[c]+beta[c]; }
}

extern "C" void kernel_launch(void* const* d_in, const int* in_sizes, int n_in,
                              void* d_out, int out_size){
  const float* x      =(const float*)d_in[0];
  const float* ipw    =(const float*)d_in[1];
  const float* cw     =(const float*)d_in[2];
  const float* cb     =(const float*)d_in[3];
  const float* xpw    =(const float*)d_in[4];
  const float* dtw    =(const float*)d_in[5];
  const float* dtb    =(const float*)d_in[6];
  const float* alogs  =(const float*)d_in[7];
  const float* dsv    =(const float*)d_in[8];
  const float* ong    =(const float*)d_in[9];
  const float* onb    =(const float*)d_in[10];
  const float* opw    =(const float*)d_in[11];
  const float* fiw    =(const float*)d_in[12];
  const float* fib    =(const float*)d_in[13];
  const float* fd1    =(const float*)d_in[14];
  const float* fd3    =(const float*)d_in[15];
  const float* fd5    =(const float*)d_in[16];
  const float* flg    =(const float*)d_in[17];
  const float* flb    =(const float*)d_in[18];
  const float* fow    =(const float*)d_in[19];
  const float* fob    =(const float*)d_in[20];
  const float* skip   =(const float*)d_in[21];
  float* out=(float*)d_out;

  float *pxz,*pygt,*phcl,*phn;
  cudaGetSymbolAddress((void**)&pxz,  g_xz);
  cudaGetSymbolAddress((void**)&pygt, g_ygt);
  cudaGetSymbolAddress((void**)&phcl, g_hcl);
  cudaGetSymbolAddress((void**)&phn,  g_hn);

  sgemm_nt<0><<<dim3(6,128),256>>>(x, ipw, pxz, 16384,384,96, nullptr,nullptr);
  t_xi<<<dim3(6,128,4),dim3(32,8)>>>();
  conv3<<<768*LL/256,256>>>(cw,cb);
  t_hw<<<dim3(2,2,768),dim3(32,8)>>>();
  xproj<<<dim3(256,16),256>>>(xpw);
  deltak<<<dim3(64,16),256>>>(dtw,dtb);
  scan<<<384,128>>>(alogs,dsv);
  combine<<<dim3(2,2,768),dim3(32,8)>>>();
  ln_gate<<<dim3(128,4),256>>>(ong,onb);
  sgemm_nt<0><<<dim3(2,128),256>>>(pygt, opw, out, 16384,96,192, nullptr,nullptr);
  sgemm_nt<1><<<dim3(12,128),256>>>(pygt, fiw, phcl, 16384,768,192, fib,nullptr);
  prep_weff<<<3,256>>>(fd1,fd3,fd5);
  conv5<<<dim3(12,8,64),dim3(16,8,4)>>>();
  ln768<<<16384,256>>>(flg,flb);
  sgemm_nt<2><<<dim3(2,128),256>>>(phn, fow, out, 16384,96,768, fob,skip);
}

// round 4
// speedup vs baseline: 1.0626x; 1.0626x over previous
#include <cuda_runtime.h>
#include <math.h>
#define LL 4096

__device__ __align__(16) float g_xz  [16384*384];
__device__ __align__(16) float g_xi  [768*LL];
__device__ __align__(16) float g_xc  [768*LL];
__device__ __align__(16) float g_xcT [768*LL];
__device__ __align__(16) float g_xdbl[16*LL*40];
__device__ __align__(16) float g_delta[16*192*LL];
__device__ __align__(16) float g_ys  [16*192*LL];
__device__ __align__(16) float g_ysum[768*LL];
__device__ __align__(16) float g_ygt [16384*192];
__device__ __align__(16) float g_hcl [16384*768];
__device__ __align__(16) float g_hc2 [16384*768];
__device__ __align__(16) float g_hn  [16384*768];
__device__ __align__(16) float g_weff[25*768];

__device__ __forceinline__ float siluf(float v){ return v/(1.f+__expf(-v)); }
__device__ __forceinline__ unsigned f2tf(float f){ unsigned u; asm("cvt.rna.tf32.f32 %0, %1;":"=r"(u):"f"(f)); return u; }
__device__ __forceinline__ void mma8(float* c, unsigned a0,unsigned a1,unsigned a2,unsigned a3,
                                     unsigned b0,unsigned b1){
  asm("mma.sync.aligned.m16n8k8.row.col.f32.tf32.tf32.f32 "
      "{%0,%1,%2,%3},{%4,%5,%6,%7},{%8,%9},{%0,%1,%2,%3};"
      : "+f"(c[0]),"+f"(c[1]),"+f"(c[2]),"+f"(c[3])
      : "r"(a0),"r"(a1),"r"(a2),"r"(a3),"r"(b0),"r"(b1));
}

// C[M,N] = A[M,K] @ W[N,K]^T via tf32 mma. MODE 0 plain, 1 bias+silu, 2 C+=skip[0]*(acc+bias)
// Block 128m x 64n x 16k, 8 warps (4m x 2n), warp tile 32x32.
// Smem k-permutation: col k -> (k%4)*4 + k/4, so a thread's frag cols {c,c+4,c+8,c+12} are one uint4.
template<int MODE>
__global__ __launch_bounds__(256) void mma_nt(
  const float* __restrict__ A, const float* __restrict__ W, float* __restrict__ C,
  int M, int N, int K, const float* __restrict__ bias, const float* __restrict__ skip)
{
  __shared__ unsigned As[128*20];
  __shared__ unsigned Bs[64*20];
  int tid=threadIdx.x, lane=tid&31, warp=tid>>5;
  int wm=warp>>1, wn=warp&1;
  int m0=blockIdx.y*128, n0=blockIdx.x*64;
  int lr=lane>>2, lc=lane&3;
  float acc[2][4][4];
  #pragma unroll
  for(int a=0;a<2;a++)
    #pragma unroll
    for(int b=0;b<4;b++)
      #pragma unroll
      for(int q=0;q<4;q++) acc[a][b][q]=0.f;

  for(int k0=0;k0<K;k0+=16){
    #pragma unroll
    for(int i=0;i<2;i++){
      int item=tid+i*256, row=item>>2, t=item&3;
      float4 v=*(const float4*)(A+(size_t)(m0+row)*K+k0+t*4);
      unsigned* p=&As[row*20];
      p[t]=f2tf(v.x); p[4+t]=f2tf(v.y); p[8+t]=f2tf(v.z); p[12+t]=f2tf(v.w);
    }
    { int row=tid>>2, t=tid&3;
      float4 v=make_float4(0,0,0,0);
      if(n0+row<N) v=*(const float4*)(W+(size_t)(n0+row)*K+k0+t*4);
      unsigned* p=&Bs[row*20];
      p[t]=f2tf(v.x); p[4+t]=f2tf(v.y); p[8+t]=f2tf(v.z); p[12+t]=f2tf(v.w);
    }
    __syncthreads();
    uint4 bg[4];
    #pragma unroll
    for(int nt=0;nt<4;nt++){
      int n=wn*32+nt*8+lr;
      bg[nt]=*(const uint4*)&Bs[n*20+lc*4];
    }
    #pragma unroll
    for(int mt=0;mt<2;mt++){
      int r0=wm*32+mt*16+lr;
      uint4 f0=*(const uint4*)&As[r0*20+lc*4];
      uint4 f1=*(const uint4*)&As[(r0+8)*20+lc*4];
      #pragma unroll
      for(int nt=0;nt<4;nt++){
        mma8(acc[mt][nt], f0.x,f1.x,f0.y,f1.y, bg[nt].x,bg[nt].y);
        mma8(acc[mt][nt], f0.z,f1.z,f0.w,f1.w, bg[nt].z,bg[nt].w);
      }
    }
    __syncthreads();
  }
  #pragma unroll
  for(int mt=0;mt<2;mt++){
    #pragma unroll
    for(int nt=0;nt<4;nt++){
      int col=n0+wn*32+nt*8+lc*2;
      if(col>=N) continue;
      int r=m0+wm*32+mt*16+lr;
      #pragma unroll
      for(int hh=0;hh<2;hh++){
        int row=r+hh*8;
        float v0=acc[mt][nt][hh*2], v1=acc[mt][nt][hh*2+1];
        size_t idx=(size_t)row*N+col;
        if(MODE==0){ C[idx]=v0; C[idx+1]=v1; }
        else if(MODE==1){
          v0+=bias[col]; v1+=bias[col+1];
          C[idx]=siluf(v0); C[idx+1]=siluf(v1);
        } else {
          float sk=skip[0];
          C[idx]+=sk*(v0+bias[col]); C[idx+1]+=sk*(v1+bias[col+1]);
        }
      }
    }
  }
}

// xz[:, :192] -> xi [b][c][l]
__global__ void t_xi(){
  __shared__ float t[32][33];
  int b=blockIdx.z, c0=blockIdx.x*32, l0=blockIdx.y*32, tx=threadIdx.x, ty=threadIdx.y;
  for(int i=0;i<4;i++) t[ty+i*8][tx]=g_xz[((size_t)b*LL+l0+ty+i*8)*384+c0+tx];
  __syncthreads();
  for(int i=0;i<4;i++) g_xi[((size_t)b*192+c0+ty+i*8)*LL+l0+tx]=t[tx][ty+i*8];
}

__global__ void conv3(const float* __restrict__ cw, const float* __restrict__ cb){
  int id=blockIdx.x*256+threadIdx.x; if(id>=768*LL) return;
  int l=id&4095, c=(id>>12)%192, h=l>>6, w=l&63;
  float s=cb[c];
  const float* base=g_xi+(size_t)(id-l);
  #pragma unroll
  for(int dy=0;dy<3;dy++){ int hh=h+dy-1; if(hh<0||hh>63) continue;
    #pragma unroll
    for(int dx=0;dx<3;dx++){ int ww=w+dx-1; if(ww<0||ww>63) continue;
      s+=base[hh*64+ww]*cw[c*9+dy*3+dx]; } }
  g_xc[id]=siluf(s);
}

__global__ void t_hw(){
  __shared__ float t[32][33];
  int bc=blockIdx.z, w0=blockIdx.x*32, h0=blockIdx.y*32, tx=threadIdx.x, ty=threadIdx.y;
  const float* s=g_xc+(size_t)bc*LL; float* d=g_xcT+(size_t)bc*LL;
  for(int i=0;i<4;i++) t[ty+i*8][tx]=s[(h0+ty+i*8)*64+w0+tx];
  __syncthreads();
  for(int i=0;i<4;i++) d[(w0+ty+i*8)*64+h0+tx]=t[tx][ty+i*8];
}

// x_dbl[bk][l][40]: cols 0..5 dts, 8..39 B/C interleaved (Bn at 8+2n, Cn at 9+2n)
__global__ __launch_bounds__(256) void xproj(const float* __restrict__ xpw){
  __shared__ float Xs[16][196];
  __shared__ float Wsm[38*192];
  int bk=blockIdx.y, b=bk>>2, k=bk&3, l0=blockIdx.x*16, tid=threadIdx.x;
  const float* src=(k&1)?g_xcT:g_xc; bool flip=(k>=2);
  for(int i=tid;i<38*192;i+=256) Wsm[i]=xpw[k*38*192+i];
  for(int i=tid;i<192*16;i+=256){ int d=i>>4, li=i&15;
    int lf=flip?(4095-(l0+li)):(l0+li);
    Xs[li][d]=src[((size_t)b*192+d)*LL+lf]; }
  __syncthreads();
  for(int o=tid;o<38*16;o+=256){ int c=o>>4, li=o&15;
    const float* wr=Wsm+c*192; const float* xr=Xs[li]; float s=0.f;
    #pragma unroll 8
    for(int d=0;d<192;d+=4){ float4 wv=*(const float4*)(wr+d), xv=*(const float4*)(xr+d);
      s+=wv.x*xv.x+wv.y*xv.y+wv.z*xv.z+wv.w*xv.w; }
    int col=(c<6)?c:(c<22?(8+2*(c-6)):(9+2*(c-22)));
    g_xdbl[((size_t)bk*LL+l0+li)*40+col]=s; }
}

__global__ __launch_bounds__(256) void deltak(const float* __restrict__ dtw, const float* __restrict__ dtb){
  int bk=blockIdx.y, l0=blockIdx.x*64, k=bk&3, tid=threadIdx.x;
  __shared__ float dts[64][6];
  for(int i=tid;i<64*6;i+=256) dts[i/6][i%6]=g_xdbl[((size_t)bk*LL+l0+i/6)*40+i%6];
  __syncthreads();
  for(int i=tid;i<192*64;i+=256){ int d=i>>6, li=i&63;
    float s=dtb[k*192+d];
    #pragma unroll
    for(int r=0;r<6;r++) s+=dts[li][r]*dtw[(k*192+d)*6+r];
    s=(s>20.f)?s:log1pf(__expf(s));
    g_delta[((size_t)bk*192+d)*LL+l0+li]=s; }
}

__global__ __launch_bounds__(128) void scan(const float* __restrict__ A_logs, const float* __restrict__ Ds){
  __shared__ float ybuf[4][2][32];
  int wIB=threadIdx.x>>5, lane=threadIdx.x&31;
  int wg=blockIdx.x*4+wIB, dpair=wg%96, bk=wg/96, b=bk>>2, k=bk&3;
  int half=lane>>4, n=lane&15, d=dpair*2+half, kd=k*192+d;
  float Av=-__expf(A_logs[kd*16+n]), Dv=Ds[kd];
  const float* xsrc=((k&1)?g_xcT:g_xc)+((size_t)b*192+d)*LL;
  const float* dsrc=g_delta+((size_t)bk*192+d)*LL;
  const float* xdb=g_xdbl+(size_t)bk*LL*40;
  bool flip=(k>=2);
  float h=0.f;
  for(int l0=0;l0<LL;l0+=32){
    #pragma unroll
    for(int s4=0;s4<32;s4+=4){
      int lb=l0+s4;
      float4 d4=*(const float4*)(dsrc+lb);
      float dls[4]={d4.x,d4.y,d4.z,d4.w}, xv[4];
      if(!flip){ float4 x4=*(const float4*)(xsrc+lb); xv[0]=x4.x;xv[1]=x4.y;xv[2]=x4.z;xv[3]=x4.w; }
      else     { float4 x4=*(const float4*)(xsrc+4092-lb); xv[0]=x4.w;xv[1]=x4.z;xv[2]=x4.y;xv[3]=x4.x; }
      #pragma unroll
      for(int i=0;i<4;i++){
        float2 bc=*(const float2*)(xdb+(size_t)(lb+i)*40+8+2*n);
        h=h*__expf(dls[i]*Av)+(dls[i]*xv[i])*bc.x;
        float yp=h*bc.y;
        yp+=__shfl_xor_sync(~0u,yp,1); yp+=__shfl_xor_sync(~0u,yp,2);
        yp+=__shfl_xor_sync(~0u,yp,4); yp+=__shfl_xor_sync(~0u,yp,8);
        if(n==0) ybuf[wIB][half][s4+i]=yp+Dv*xv[i];
      }
    }
    __syncwarp();
    #pragma unroll
    for(int hh=0;hh<2;hh++){
      size_t ob=(((size_t)k*4+b)*192+dpair*2+hh)*LL;
      int pos=flip?(4095-(l0+lane)):(l0+lane);
      g_ys[ob+pos]=ybuf[wIB][hh][lane];
    }
    __syncwarp();
  }
}

// ysum[b][c][h*64+w] = Y0+Y2 at hw + transpose(Y1+Y3)
__global__ void combine(){
  __shared__ float t[32][33];
  int bc=blockIdx.z, w0=blockIdx.x*32, h0=blockIdx.y*32, tx=threadIdx.x, ty=threadIdx.y;
  const float* Y0=g_ys+(size_t)bc*LL;         const float* Y1=g_ys+(size_t)(768+bc)*LL;
  const float* Y2=g_ys+(size_t)(1536+bc)*LL;  const float* Y3=g_ys+(size_t)(2304+bc)*LL;
  for(int i=0;i<4;i++){ int wl=ty+i*8, j=(w0+wl)*64+h0+tx; t[wl][tx]=Y1[j]+Y3[j]; }
  __syncthreads();
  float* o=g_ysum+(size_t)bc*LL;
  for(int i=0;i<4;i++){ int hl=ty+i*8, l=(h0+hl)*64+w0+tx; o[l]=t[tx][hl]+Y0[l]+Y2[l]; }
}

__global__ __launch_bounds__(256) void ln_gate(const float* __restrict__ g, const float* __restrict__ beta){
  __shared__ float t[192][33];
  int b=blockIdx.y, l0=blockIdx.x*32, tid=threadIdx.x;
  for(int i=tid;i<192*32;i+=256) t[i>>5][i&31]=g_ysum[((size_t)b*192+(i>>5))*LL+l0+(i&31)];
  __syncthreads();
  int warp=tid>>5, lane=tid&31;
  for(int q=0;q<4;q++){
    int li=warp*4+q, l=l0+li;
    float s=0.f,s2=0.f,v[6];
    #pragma unroll
    for(int i=0;i<6;i++){ v[i]=t[lane+32*i][li]; s+=v[i]; s2+=v[i]*v[i]; }
    #pragma unroll
    for(int o=16;o;o>>=1){ s+=__shfl_xor_sync(~0u,s,o); s2+=__shfl_xor_sync(~0u,s2,o); }
    float mean=s/192.f, var=s2/192.f-mean*mean, rstd=rsqrtf(var+1e-5f);
    #pragma unroll
    for(int i=0;i<6;i++){ int c=lane+32*i;
      float zz=g_xz[((size_t)b*LL+l)*384+192+c];
      g_ygt[((size_t)b*LL+l)*192+c]=((v[i]-mean)*rstd*g[c]+beta[c])*siluf(zz); }
  }
}

__global__ void prep_weff(const float* __restrict__ d1,const float* __restrict__ d3,const float* __restrict__ d5){
  int c=blockIdx.x*256+threadIdx.x; if(c>=768) return;
  for(int t=0;t<25;t++){ int dy=t/5,dx=t%5;
    float w=d5[c*25+t];
    if(dy>=1&&dy<=3&&dx>=1&&dx<=3) w+=d3[c*9+(dy-1)*3+(dx-1)];
    if(t==12) w+=d1[c]+1.0f;
    g_weff[t*768+c]=w; }
}

__global__ __launch_bounds__(512) void conv5(){
  __shared__ float4 tile[8][12][16];
  int cg=blockIdx.x, w0=blockIdx.y*8, b=blockIdx.z>>4, h0=(blockIdx.z&15)*4;
  int tid=threadIdx.x+threadIdx.y*16+threadIdx.z*128;
  for(int t=tid;t<8*12*16;t+=512){
    int r=t/192, cc=(t%192)/16, c4=t&15;
    int h=h0-2+r, w=w0-2+cc;
    float4 v=make_float4(0,0,0,0);
    if(h>=0&&h<64&&w>=0&&w<64)
      v=*(const float4*)(g_hcl+((size_t)(b*LL+h*64+w))*768+cg*64+c4*4);
    tile[r][cc][c4]=v;
  }
  __syncthreads();
  int c4=threadIdx.x, iw=threadIdx.y, ih=threadIdx.z;
  float4 a=make_float4(0,0,0,0);
  #pragma unroll
  for(int dy=0;dy<5;dy++)
    #pragma unroll
    for(int dx=0;dx<5;dx++){
      float4 xv=tile[ih+dy][iw+dx][c4];
      float4 wv=*(const float4*)(g_weff+(dy*5+dx)*768+cg*64+c4*4);
      a.x=fmaf(xv.x,wv.x,a.x); a.y=fmaf(xv.y,wv.y,a.y);
      a.z=fmaf(xv.z,wv.z,a.z); a.w=fmaf(xv.w,wv.w,a.w);
    }
  *(float4*)(g_hc2+((size_t)(b*LL+(h0+ih)*64+w0+iw))*768+cg*64+c4*4)=a;
}

__global__ __launch_bounds__(256) void ln768(const float* __restrict__ g, const float* __restrict__ beta){
  int m=blockIdx.x;
  const float* row=g_hc2+(size_t)m*768;
  float v[3], s=0.f, s2=0.f;
  #pragma unroll
  for(int i=0;i<3;i++){ v[i]=row[threadIdx.x+256*i]; s+=v[i]; s2+=v[i]*v[i]; }
  #pragma unroll
  for(int o=16;o;o>>=1){ s+=__shfl_xor_sync(~0u,s,o); s2+=__shfl_xor_sync(~0u,s2,o); }
  __shared__ float red[2][8];
  int warp=threadIdx.x>>5, lane=threadIdx.x&31;
  if(lane==0){ red[0][warp]=s; red[1][warp]=s2; }
  __syncthreads();
  float ts=0.f,ts2=0.f;
  #pragma unroll
  for(int i=0;i<8;i++){ ts+=red[0][i]; ts2+=red[1][i]; }
  float mean=ts/768.f, var=ts2/768.f-mean*mean, rstd=rsqrtf(var+1e-5f);
  #pragma unroll
  for(int i=0;i<3;i++){ int c=threadIdx.x+256*i;
    g_hn[(size_t)m*768+c]=(v[i]-mean)*rstd*g[c]+beta[c]; }
}

extern "C" void kernel_launch(void* const* d_in, const int* in_sizes, int n_in,
                              void* d_out, int out_size){
  const float* x      =(const float*)d_in[0];
  const float* ipw    =(const float*)d_in[1];
  const float* cw     =(const float*)d_in[2];
  const float* cb     =(const float*)d_in[3];
  const float* xpw    =(const float*)d_in[4];
  const float* dtw    =(const float*)d_in[5];
  const float* dtb    =(const float*)d_in[6];
  const float* alogs  =(const float*)d_in[7];
  const float* dsv    =(const float*)d_in[8];
  const float* ong    =(const float*)d_in[9];
  const float* onb    =(const float*)d_in[10];
  const float* opw    =(const float*)d_in[11];
  const float* fiw    =(const float*)d_in[12];
  const float* fib    =(const float*)d_in[13];
  const float* fd1    =(const float*)d_in[14];
  const float* fd3    =(const float*)d_in[15];
  const float* fd5    =(const float*)d_in[16];
  const float* flg    =(const float*)d_in[17];
  const float* flb    =(const float*)d_in[18];
  const float* fow    =(const float*)d_in[19];
  const float* fob    =(const float*)d_in[20];
  const float* skip   =(const float*)d_in[21];
  float* out=(float*)d_out;

  float *pxz,*pygt,*phcl,*phn;
  cudaGetSymbolAddress((void**)&pxz,  g_xz);
  cudaGetSymbolAddress((void**)&pygt, g_ygt);
  cudaGetSymbolAddress((void**)&phcl, g_hcl);
  cudaGetSymbolAddress((void**)&phn,  g_hn);

  mma_nt<0><<<dim3(6,128),256>>>(x, ipw, pxz, 16384,384,96, nullptr,nullptr);
  t_xi<<<dim3(6,128,4),dim3(32,8)>>>();
  conv3<<<768*LL/256,256>>>(cw,cb);
  t_hw<<<dim3(2,2,768),dim3(32,8)>>>();
  xproj<<<dim3(256,16),256>>>(xpw);
  deltak<<<dim3(64,16),256>>>(dtw,dtb);
  scan<<<384,128>>>(alogs,dsv);
  combine<<<dim3(2,2,768),dim3(32,8)>>>();
  ln_gate<<<dim3(128,4),256>>>(ong,onb);
  mma_nt<0><<<dim3(2,128),256>>>(pygt, opw, out, 16384,96,192, nullptr,nullptr);
  mma_nt<1><<<dim3(12,128),256>>>(pygt, fiw, phcl, 16384,768,192, fib,nullptr);
  prep_weff<<<3,256>>>(fd1,fd3,fd5);
  conv5<<<dim3(12,8,64),dim3(16,8,4)>>>();
  ln768<<<16384,256>>>(flg,flb);
  mma_nt<2><<<dim3(2,128),256>>>(phn, fow, out, 16384,96,768, fob,skip);
}

// round 6
// speedup vs baseline: 1.1419x; 1.0747x over previous
#include <cuda_runtime.h>
#include <math.h>
#define LL 4096

__device__ __align__(16) float g_xz  [16384*384];
__device__ __align__(16) float g_xi  [768*LL];
__device__ __align__(16) float g_xc  [768*LL];
__device__ __align__(16) float g_xcT [768*LL];
__device__ __align__(16) float g_xdbl[16*LL*40];
__device__ __align__(16) float g_delta[16*192*LL];
__device__ __align__(16) float g_ys  [16*192*LL];
__device__ __align__(16) float g_ysum[768*LL];
__device__ __align__(16) float g_ygt [16384*192];
__device__ __align__(16) float g_hcl [16384*768];
__device__ __align__(16) float g_hc2 [16384*768];
__device__ __align__(16) float g_weff[25*768];
__device__ __align__(16) float g_wg  [96*768];
__device__ __align__(16) float g_ps  [16384*12];
__device__ __align__(16) float g_ps2 [16384*12];
__device__ float g_rowm[16384];
__device__ float g_rowr[16384];
__device__ float g_csum[96];
__device__ float g_cb2 [96];

__device__ __forceinline__ float siluf(float v){ return v/(1.f+__expf(-v)); }
__device__ __forceinline__ unsigned f2tf(float f){ unsigned u; asm("cvt.rna.tf32.f32 %0, %1;":"=r"(u):"f"(f)); return u; }
__device__ __forceinline__ void mma8(float* c, unsigned a0,unsigned a1,unsigned a2,unsigned a3,
                                     unsigned b0,unsigned b1){
  asm("mma.sync.aligned.m16n8k8.row.col.f32.tf32.tf32.f32 "
      "{%0,%1,%2,%3},{%4,%5,%6,%7},{%8,%9},{%0,%1,%2,%3};"
      : "+f"(c[0]),"+f"(c[1]),"+f"(c[2]),"+f"(c[3])
      : "r"(a0),"r"(a1),"r"(a2),"r"(a3),"r"(b0),"r"(b1));
}

// C[M,N] = A[M,K]@W[N,K]^T, tf32 tensor cores. 128x128x16 tile, 8 warps (2m x 4n),
// warp tile 64x32, register double-buffered global loads.
// MODE 0: plain   1: bias+silu   3: C += skip[0]*((v - rowm[m]*csum[n])*rowr[m] + cb2[n])
template<int MODE>
__global__ __launch_bounds__(256,2) void gemm_tc(
  const float* __restrict__ A, const float* __restrict__ W, float* __restrict__ C,
  int M, int N, int K, const float* __restrict__ bias, const float* __restrict__ skip,
  const float* __restrict__ rowm, const float* __restrict__ rowr,
  const float* __restrict__ csum, const float* __restrict__ cb2)
{
  __shared__ unsigned As[128*20];
  __shared__ unsigned Bs[128*20];
  int tid=threadIdx.x, lane=tid&31, warp=tid>>5;
  int wm=warp>>2, wn=warp&3;
  int m0=blockIdx.y*128, n0=blockIdx.x*128;
  int lr=lane>>2, lc=lane&3;
  float acc[4][4][4];
  #pragma unroll
  for(int a=0;a<4;a++)
    #pragma unroll
    for(int b=0;b<4;b++)
      #pragma unroll
      for(int q=0;q<4;q++) acc[a][b][q]=0.f;

  int row0=tid>>2, t0=tid&3;
  float4 ra[2], rb[2];
  #pragma unroll
  for(int i=0;i<2;i++){
    int row=row0+i*64;
    ra[i]=*(const float4*)(A+(size_t)(m0+row)*K + t0*4);
    int br=n0+row;
    rb[i]= (br<N) ? *(const float4*)(W+(size_t)br*K + t0*4) : make_float4(0,0,0,0);
  }
  for(int k0=0;k0<K;k0+=16){
    #pragma unroll
    for(int i=0;i<2;i++){
      int row=row0+i*64;
      unsigned* p=&As[row*20];
      p[t0]=f2tf(ra[i].x); p[4+t0]=f2tf(ra[i].y); p[8+t0]=f2tf(ra[i].z); p[12+t0]=f2tf(ra[i].w);
      unsigned* q=&Bs[row*20];
      q[t0]=f2tf(rb[i].x); q[4+t0]=f2tf(rb[i].y); q[8+t0]=f2tf(rb[i].z); q[12+t0]=f2tf(rb[i].w);
    }
    __syncthreads();
    if(k0+16<K){
      #pragma unroll
      for(int i=0;i<2;i++){
        int row=row0+i*64;
        ra[i]=*(const float4*)(A+(size_t)(m0+row)*K + k0+16 + t0*4);
        int br=n0+row;
        rb[i]= (br<N) ? *(const float4*)(W+(size_t)br*K + k0+16 + t0*4) : make_float4(0,0,0,0);
      }
    }
    uint4 bg[4];
    #pragma unroll
    for(int nt=0;nt<4;nt++) bg[nt]=*(const uint4*)&Bs[(wn*32+nt*8+lr)*20+lc*4];
    #pragma unroll
    for(int mt=0;mt<4;mt++){
      int r0=wm*64+mt*16+lr;
      uint4 f0=*(const uint4*)&As[r0*20+lc*4];
      uint4 f1=*(const uint4*)&As[(r0+8)*20+lc*4];
      #pragma unroll
      for(int nt=0;nt<4;nt++){
        mma8(acc[mt][nt], f0.x,f1.x,f0.y,f1.y, bg[nt].x,bg[nt].y);
        mma8(acc[mt][nt], f0.z,f1.z,f0.w,f1.w, bg[nt].z,bg[nt].w);
      }
    }
    __syncthreads();
  }
  #pragma unroll
  for(int mt=0;mt<4;mt++){
    #pragma unroll
    for(int nt=0;nt<4;nt++){
      int col=n0+wn*32+nt*8+lc*2;
      if(col>=N) continue;
      #pragma unroll
      for(int hh=0;hh<2;hh++){
        int row=m0+wm*64+mt*16+lr+hh*8;
        float v0=acc[mt][nt][hh*2], v1=acc[mt][nt][hh*2+1];
        size_t idx=(size_t)row*N+col;
        if(MODE==0){ C[idx]=v0; C[idx+1]=v1; }
        else if(MODE==1){
          v0+=bias[col]; v1+=bias[col+1];
          C[idx]=siluf(v0); C[idx+1]=siluf(v1);
        } else {
          float sk=skip[0], mn=rowm[row], rs=rowr[row];
          C[idx]  += sk*((v0-mn*csum[col  ])*rs + cb2[col  ]);
          C[idx+1]+= sk*((v1-mn*csum[col+1])*rs + cb2[col+1]);
        }
      }
    }
  }
}

// xz[:, :192] -> xi [b][c][l]
__global__ void t_xi(){
  __shared__ float t[32][33];
  int b=blockIdx.z, c0=blockIdx.x*32, l0=blockIdx.y*32, tx=threadIdx.x, ty=threadIdx.y;
  for(int i=0;i<4;i++) t[ty+i*8][tx]=g_xz[((size_t)b*LL+l0+ty+i*8)*384+c0+tx];
  __syncthreads();
  for(int i=0;i<4;i++) g_xi[((size_t)b*192+c0+ty+i*8)*LL+l0+tx]=t[tx][ty+i*8];
}

// depthwise 3x3 + bias + silu, writes both xc (hw) and xcT (wh) coalesced
__global__ __launch_bounds__(256) void conv3t(const float* __restrict__ cw, const float* __restrict__ cb){
  __shared__ float pl[66*66];
  __shared__ float ot[64*65];
  int bc=blockIdx.x, c=bc%192;
  const float* src=g_xi+(size_t)bc*4096;
  float wr[9];
  #pragma unroll
  for(int i=0;i<9;i++) wr[i]=cw[c*9+i];
  float bv=cb[c];
  for(int i=threadIdx.x;i<4356;i+=256){
    int r=i/66, q=i-r*66, h=r-1, w=q-1;
    pl[i]=(h>=0&&h<64&&w>=0&&w<64)? src[h*64+w] : 0.f;
  }
  __syncthreads();
  float* dst=g_xc+(size_t)bc*4096;
  for(int p=threadIdx.x;p<4096;p+=256){
    int h=p>>6, w=p&63;
    float s=bv;
    #pragma unroll
    for(int dy=0;dy<3;dy++)
      #pragma unroll
      for(int dx=0;dx<3;dx++) s+=pl[(h+dy)*66+w+dx]*wr[dy*3+dx];
    s=siluf(s);
    dst[p]=s; ot[h*65+w]=s;
  }
  __syncthreads();
  float* dT=g_xcT+(size_t)bc*4096;
  for(int p=threadIdx.x;p<4096;p+=256){
    int wq=p>>6, hq=p&63;
    dT[p]=ot[hq*65+wq];
  }
}

// x_dbl[bk][l][40]: cols 0..5 dts, 8..39 B/C interleaved (Bn at 8+2n, Cn at 9+2n)
__global__ __launch_bounds__(256) void xproj(const float* __restrict__ xpw){
  __shared__ float Xs[16][196];
  __shared__ float Wsm[38*192];
  int bk=blockIdx.y, b=bk>>2, k=bk&3, l0=blockIdx.x*16, tid=threadIdx.x;
  const float* src=(k&1)?g_xcT:g_xc; bool flip=(k>=2);
  for(int i=tid;i<38*192;i+=256) Wsm[i]=xpw[k*38*192+i];
  for(int i=tid;i<192*16;i+=256){ int d=i>>4, li=i&15;
    int lf=flip?(4095-(l0+li)):(l0+li);
    Xs[li][d]=src[((size_t)b*192+d)*LL+lf]; }
  __syncthreads();
  for(int o=tid;o<38*16;o+=256){ int c=o>>4, li=o&15;
    const float* wr=Wsm+c*192; const float* xr=Xs[li]; float s=0.f;
    #pragma unroll 8
    for(int d=0;d<192;d+=4){ float4 wv=*(const float4*)(wr+d), xv=*(const float4*)(xr+d);
      s+=wv.x*xv.x+wv.y*xv.y+wv.z*xv.z+wv.w*xv.w; }
    int col=(c<6)?c:(c<22?(8+2*(c-6)):(9+2*(c-22)));
    g_xdbl[((size_t)bk*LL+l0+li)*40+col]=s; }
}

__global__ __launch_bounds__(256) void deltak(const float* __restrict__ dtw, const float* __restrict__ dtb){
  int bk=blockIdx.y, l0=blockIdx.x*64, k=bk&3, tid=threadIdx.x;
  __shared__ float dts[64][6];
  for(int i=tid;i<64*6;i+=256) dts[i/6][i%6]=g_xdbl[((size_t)bk*LL+l0+i/6)*40+i%6];
  __syncthreads();
  for(int i=tid;i<192*64;i+=256){ int d=i>>6, li=i&63;
    float s=dtb[k*192+d];
    #pragma unroll
    for(int r=0;r<6;r++) s+=dts[li][r]*dtw[(k*192+d)*6+r];
    s=(s>20.f)?s:log1pf(__expf(s));
    g_delta[((size_t)bk*192+d)*LL+l0+li]=s; }
}

__global__ __launch_bounds__(128) void scan(const float* __restrict__ A_logs, const float* __restrict__ Ds){
  __shared__ float ybuf[4][2][32];
  int wIB=threadIdx.x>>5, lane=threadIdx.x&31;
  int wg=blockIdx.x*4+wIB, dpair=wg%96, bk=wg/96, b=bk>>2, k=bk&3;
  int half=lane>>4, n=lane&15, d=dpair*2+half, kd=k*192+d;
  float Av=-__expf(A_logs[kd*16+n]), Dv=Ds[kd];
  const float* xsrc=((k&1)?g_xcT:g_xc)+((size_t)b*192+d)*LL;
  const float* dsrc=g_delta+((size_t)bk*192+d)*LL;
  const float* xdb=g_xdbl+(size_t)bk*LL*40;
  bool flip=(k>=2);
  float h=0.f;
  for(int l0=0;l0<LL;l0+=32){
    #pragma unroll
    for(int s4=0;s4<32;s4+=4){
      int lb=l0+s4;
      float4 d4=*(const float4*)(dsrc+lb);
      float dls[4]={d4.x,d4.y,d4.z,d4.w}, xv[4];
      if(!flip){ float4 x4=*(const float4*)(xsrc+lb); xv[0]=x4.x;xv[1]=x4.y;xv[2]=x4.z;xv[3]=x4.w; }
      else     { float4 x4=*(const float4*)(xsrc+4092-lb); xv[0]=x4.w;xv[1]=x4.z;xv[2]=x4.y;xv[3]=x4.x; }
      #pragma unroll
      for(int i=0;i<4;i++){
        float2 bc=*(const float2*)(xdb+(size_t)(lb+i)*40+8+2*n);
        h=h*__expf(dls[i]*Av)+(dls[i]*xv[i])*bc.x;
        float yp=h*bc.y;
        yp+=__shfl_xor_sync(~0u,yp,1); yp+=__shfl_xor_sync(~0u,yp,2);
        yp+=__shfl_xor_sync(~0u,yp,4); yp+=__shfl_xor_sync(~0u,yp,8);
        if(n==0) ybuf[wIB][half][s4+i]=yp+Dv*xv[i];
      }
    }
    __syncwarp();
    #pragma unroll
    for(int hh=0;hh<2;hh++){
      size_t ob=(((size_t)k*4+b)*192+dpair*2+hh)*LL;
      int pos=flip?(4095-(l0+lane)):(l0+lane);
      g_ys[ob+pos]=ybuf[wIB][hh][lane];
    }
    __syncwarp();
  }
}

// ysum[b][c][h*64+w] = Y0+Y2 at hw + transpose(Y1+Y3)
__global__ void combine(){
  __shared__ float t[32][33];
  int bc=blockIdx.z, w0=blockIdx.x*32, h0=blockIdx.y*32, tx=threadIdx.x, ty=threadIdx.y;
  const float* Y0=g_ys+(size_t)bc*LL;         const float* Y1=g_ys+(size_t)(768+bc)*LL;
  const float* Y2=g_ys+(size_t)(1536+bc)*LL;  const float* Y3=g_ys+(size_t)(2304+bc)*LL;
  for(int i=0;i<4;i++){ int wl=ty+i*8, j=(w0+wl)*64+h0+tx; t[wl][tx]=Y1[j]+Y3[j]; }
  __syncthreads();
  float* o=g_ysum+(size_t)bc*LL;
  for(int i=0;i<4;i++){ int hl=ty+i*8, l=(h0+hl)*64+w0+tx; o[l]=t[tx][hl]+Y0[l]+Y2[l]; }
}

__global__ __launch_bounds__(256) void ln_gate(const float* __restrict__ g, const float* __restrict__ beta){
  __shared__ float t[192][33];
  int b=blockIdx.y, l0=blockIdx.x*32, tid=threadIdx.x;
  for(int i=tid;i<192*32;i+=256) t[i>>5][i&31]=g_ysum[((size_t)b*192+(i>>5))*LL+l0+(i&31)];
  __syncthreads();
  int warp=tid>>5, lane=tid&31;
  for(int q=0;q<4;q++){
    int li=warp*4+q, l=l0+li;
    float s=0.f,s2=0.f,v[6];
    #pragma unroll
    for(int i=0;i<6;i++){ v[i]=t[lane+32*i][li]; s+=v[i]; s2+=v[i]*v[i]; }
    #pragma unroll
    for(int o=16;o;o>>=1){ s+=__shfl_xor_sync(~0u,s,o); s2+=__shfl_xor_sync(~0u,s2,o); }
    float mean=s/192.f, var=s2/192.f-mean*mean, rstd=rsqrtf(var+1e-5f);
    #pragma unroll
    for(int i=0;i<6;i++){ int c=lane+32*i;
      float zz=g_xz[((size_t)b*LL+l)*384+192+c];
      g_ygt[((size_t)b*LL+l)*192+c]=((v[i]-mean)*rstd*g[c]+beta[c])*siluf(zz); }
  }
}

__global__ void prep_weff(const float* __restrict__ d1,const float* __restrict__ d3,const float* __restrict__ d5){
  int c=blockIdx.x*256+threadIdx.x; if(c>=768) return;
  for(int t=0;t<25;t++){ int dy=t/5,dx=t%5;
    float w=d5[c*25+t];
    if(dy>=1&&dy<=3&&dx>=1&&dx<=3) w+=d3[c*9+(dy-1)*3+(dx-1)];
    if(t==12) w+=d1[c]+1.0f;
    g_weff[t*768+c]=w; }
}

// Wg[n,c]=fow[n,c]*g[c];  csum[n]=sum_c Wg;  cb2[n]=sum_c fow*beta + fob[n]
__global__ __launch_bounds__(256) void prep_wg(const float* __restrict__ fow, const float* __restrict__ flg,
                                               const float* __restrict__ flb, const float* __restrict__ fob){
  __shared__ float r1[8], r2[8];
  int n=blockIdx.x, tid=threadIdx.x;
  float s1=0.f, s2=0.f;
  for(int c=tid;c<768;c+=256){
    float w=fow[n*768+c], wg=w*flg[c];
    g_wg[n*768+c]=wg; s1+=wg; s2+=w*flb[c];
  }
  #pragma unroll
  for(int o=16;o;o>>=1){ s1+=__shfl_xor_sync(~0u,s1,o); s2+=__shfl_xor_sync(~0u,s2,o); }
  int warp=tid>>5, lane=tid&31;
  if(lane==0){ r1[warp]=s1; r2[warp]=s2; }
  __syncthreads();
  if(tid==0){
    float t1=0.f,t2=0.f;
    #pragma unroll
    for(int i=0;i<8;i++){ t1+=r1[i]; t2+=r2[i]; }
    g_csum[n]=t1; g_cb2[n]=t2+fob[n];
  }
}

// fused effective 5x5 depthwise conv + per-pixel partial sum/sumsq over its 64 channels
__global__ __launch_bounds__(512) void conv5(){
  __shared__ float4 tile[8][12][16];
  int cg=blockIdx.x, w0=blockIdx.y*8, b=blockIdx.z>>4, h0=(blockIdx.z&15)*4;
  int tid=threadIdx.x+threadIdx.y*16+threadIdx.z*128;
  for(int t=tid;t<8*12*16;t+=512){
    int r=t/192, cc=(t%192)/16, c4=t&15;
    int h=h0-2+r, w=w0-2+cc;
    float4 v=make_float4(0,0,0,0);
    if(h>=0&&h<64&&w>=0&&w<64)
      v=*(const float4*)(g_hcl+((size_t)(b*LL+h*64+w))*768+cg*64+c4*4);
    tile[r][cc][c4]=v;
  }
  __syncthreads();
  int c4=threadIdx.x, iw=threadIdx.y, ih=threadIdx.z;
  float4 a=make_float4(0,0,0,0);
  #pragma unroll
  for(int dy=0;dy<5;dy++)
    #pragma unroll
    for(int dx=0;dx<5;dx++){
      float4 xv=tile[ih+dy][iw+dx][c4];
      float4 wv=*(const float4*)(g_weff+(dy*5+dx)*768+cg*64+c4*4);
      a.x=fmaf(xv.x,wv.x,a.x); a.y=fmaf(xv.y,wv.y,a.y);
      a.z=fmaf(xv.z,wv.z,a.z); a.w=fmaf(xv.w,wv.w,a.w);
    }
  int px=b*LL+(h0+ih)*64+w0+iw;
  *(float4*)(g_hc2+(size_t)px*768+cg*64+c4*4)=a;
  float s=a.x+a.y+a.z+a.w;
  float s2=a.x*a.x+a.y*a.y+a.z*a.z+a.w*a.w;
  #pragma unroll
  for(int o=1;o<16;o<<=1){ s+=__shfl_xor_sync(~0u,s,o); s2+=__shfl_xor_sync(~0u,s2,o); }
  int lane=tid&31;
  if((lane&15)==0){ g_ps[px*12+cg]=s; g_ps2[px*12+cg]=s2; }
}

__global__ void stats(){
  int px=blockIdx.x*256+threadIdx.x; if(px>=16384) return;
  float s=0.f, s2=0.f;
  #pragma unroll
  for(int j=0;j<12;j++){ s+=g_ps[px*12+j]; s2+=g_ps2[px*12+j]; }
  float mean=s*(1.f/768.f), var=s2*(1.f/768.f)-mean*mean;
  g_rowm[px]=mean; g_rowr[px]=rsqrtf(var+1e-5f);
}

extern "C" void kernel_launch(void* const* d_in, const int* in_sizes, int n_in,
                              void* d_out, int out_size){
  const float* x    =(const float*)d_in[0];
  const float* ipw  =(const float*)d_in[1];
  const float* cw   =(const float*)d_in[2];
  const float* cb   =(const float*)d_in[3];
  const float* xpw  =(const float*)d_in[4];
  const float* dtw  =(const float*)d_in[5];
  const float* dtb  =(const float*)d_in[6];
  const float* alogs=(const float*)d_in[7];
  const float* dsv  =(const float*)d_in[8];
  const float* ong  =(const float*)d_in[9];
  const float* onb  =(const float*)d_in[10];
  const float* opw  =(const float*)d_in[11];
  const float* fiw  =(const float*)d_in[12];
  const float* fib  =(const float*)d_in[13];
  const float* fd1  =(const float*)d_in[14];
  const float* fd3  =(const float*)d_in[15];
  const float* fd5  =(const float*)d_in[16];
  const float* flg  =(const float*)d_in[17];
  const float* flb  =(const float*)d_in[18];
  const float* fow  =(const float*)d_in[19];
  const float* fob  =(const float*)d_in[20];
  const float* skip =(const float*)d_in[21];
  float* out=(float*)d_out;

  float *pxz,*pygt,*phcl,*phc2,*pwg,*prm,*prr,*pcs,*pc2;
  cudaGetSymbolAddress((void**)&pxz,  g_xz);
  cudaGetSymbolAddress((void**)&pygt, g_ygt);
  cudaGetSymbolAddress((void**)&phcl, g_hcl);
  cudaGetSymbolAddress((void**)&phc2, g_hc2);
  cudaGetSymbolAddress((void**)&pwg,  g_wg);
  cudaGetSymbolAddress((void**)&prm,  g_rowm);
  cudaGetSymbolAddress((void**)&prr,  g_rowr);
  cudaGetSymbolAddress((void**)&pcs,  g_csum);
  cudaGetSymbolAddress((void**)&pc2,  g_cb2);

  gemm_tc<0><<<dim3(3,128),256>>>(x, ipw, pxz, 16384,384,96, nullptr,nullptr,nullptr,nullptr,nullptr,nullptr);
  t_xi<<<dim3(6,128,4),dim3(32,8)>>>();
  conv3t<<<768,256>>>(cw,cb);
  xproj<<<dim3(256,16),256>>>(xpw);
  deltak<<<dim3(64,16),256>>>(dtw,dtb);
  scan<<<384,128>>>(alogs,dsv);
  combine<<<dim3(2,2,768),dim3(32,8)>>>();
  ln_gate<<<dim3(128,4),256>>>(ong,onb);
  gemm_tc<0><<<dim3(1,128),256>>>(pygt, opw, out, 16384,96,192, nullptr,nullptr,nullptr,nullptr,nullptr,nullptr);
  gemm_tc<1><<<dim3(6,128),256>>>(pygt, fiw, phcl, 16384,768,192, fib,nullptr,nullptr,nullptr,nullptr,nullptr);
  prep_weff<<<3,256>>>(fd1,fd3,fd5);
  conv5<<<dim3(12,8,64),dim3(16,8,4)>>>();
  stats<<<64,256>>>();
  prep_wg<<<96,256>>>(fow,flg,flb,fob);
  gemm_tc<3><<<dim3(1,128),256>>>(phc2, pwg, out, 16384,96,768, nullptr,skip,prm,prr,pcs,pc2);
}